// round 1
// baseline (speedup 1.0000x reference)
#include <cuda_runtime.h>
#include <cuda_bf16.h>

#define NN 50000
#define EE 800000
#define DD 128
#define GG 64
#define NEG_SLOPE 0.2f

// ---------------- scratch (static device globals; no allocations) ------------
__device__ float g_h[NN * DD];     // current node features
__device__ float g_hW[NN * DD];    // projected features (h @ W)
__device__ float g_as[NN];         // per-node alpha_src dot
__device__ float g_ad[NN];         // per-node alpha_dst dot
__device__ int   g_off[NN + 1];    // CSR offsets (by destination)
__device__ int   g_cur[NN];        // scatter cursors
__device__ int   g_nbr[EE];        // CSR neighbor (source) list
__device__ int   g_deg[NN];        // in-degree histogram
__device__ float g_pool[GG * DD];  // pooled sums
__device__ float g_cnt[GG];        // nodes per graph

__device__ __forceinline__ float lrelu(float x) {
    return x > 0.f ? x : NEG_SLOPE * x;
}

// ---------------- init ----------------
__global__ void k_zero() {
    int i = blockIdx.x * blockDim.x + threadIdx.x;
    if (i < NN) g_deg[i] = 0;
    if (i < GG * DD) g_pool[i] = 0.f;
    if (i < GG) g_cnt[i] = 0.f;
}

// ---------------- CSR build ----------------
__global__ void k_count(const int* __restrict__ dst) {
    int e = blockIdx.x * blockDim.x + threadIdx.x;
    if (e < EE) atomicAdd(&g_deg[dst[e]], 1);
}

__global__ void k_scan() {
    __shared__ int wsum[32];
    __shared__ int carry;
    int tid = threadIdx.x;
    if (tid == 0) carry = 0;
    __syncthreads();
    for (int base = 0; base < NN; base += 1024) {
        int idx = base + tid;
        int v = (idx < NN) ? g_deg[idx] : 0;
        int x = v;
#pragma unroll
        for (int o = 1; o < 32; o <<= 1) {
            int y = __shfl_up_sync(0xffffffffu, x, o);
            if ((tid & 31) >= o) x += y;
        }
        if ((tid & 31) == 31) wsum[tid >> 5] = x;
        __syncthreads();
        if (tid < 32) {
            int w = wsum[tid];
#pragma unroll
            for (int o = 1; o < 32; o <<= 1) {
                int y = __shfl_up_sync(0xffffffffu, w, o);
                if (tid >= o) w += y;
            }
            wsum[tid] = w;
        }
        __syncthreads();
        int incl = x + ((tid >= 32) ? wsum[(tid >> 5) - 1] : 0);
        int base_carry = carry;
        if (idx < NN) {
            int ex = base_carry + incl - v;
            g_off[idx] = ex;
            g_cur[idx] = ex;
        }
        __syncthreads();
        if (tid == 1023) carry = base_carry + incl;
        __syncthreads();
    }
    if (tid == 0) g_off[NN] = carry;
}

__global__ void k_fill(const int* __restrict__ src, const int* __restrict__ dst) {
    int e = blockIdx.x * blockDim.x + threadIdx.x;
    if (e < EE) {
        int p = atomicAdd(&g_cur[dst[e]], 1);
        g_nbr[p] = src[e];
    }
}

// ---------------- GEMM: C[N,128] = A[N,128] @ W[128,128] (+bias) -------------
// modes: useExt -> A = Aext else g_h; outToH -> C = g_h else g_hW
__global__ void k_gemm(const float* __restrict__ Aext, int useExt,
                       const float* __restrict__ W,
                       const float* __restrict__ bias, int addBias, int outToH) {
    __shared__ float Ws[64 * DD];    // 32 KB (one K-half of W)
    __shared__ float As[32][DD];     // 16 KB

    const float* __restrict__ A = useExt ? Aext : g_h;
    float* __restrict__ C = outToH ? g_h : g_hW;

    int tid = threadIdx.x;           // 256
    int row0 = blockIdx.x * 32;

    // load A tile (32 rows x 128 cols)
    for (int i = tid; i < 32 * DD / 4; i += 256) {
        int r = i >> 5;
        int c4 = (i & 31) << 2;
        int gr = row0 + r;
        float4 v = make_float4(0.f, 0.f, 0.f, 0.f);
        if (gr < NN) v = *(const float4*)&A[gr * DD + c4];
        *(float4*)&As[r][c4] = v;
    }

    int warp = tid >> 5, lane = tid & 31;
    int r0 = warp << 2;              // 4 rows per warp
    int c = lane << 2;               // 4 cols per lane

    float4 acc0 = make_float4(0, 0, 0, 0);
    float4 acc1 = make_float4(0, 0, 0, 0);
    float4 acc2 = make_float4(0, 0, 0, 0);
    float4 acc3 = make_float4(0, 0, 0, 0);

    for (int kb = 0; kb < 2; kb++) {
        __syncthreads();
        // load W half: rows [kb*64, kb*64+64)
        for (int i = tid; i < 64 * DD / 4; i += 256) {
            *(float4*)&Ws[i * 4] = *(const float4*)&W[kb * 64 * DD + i * 4];
        }
        __syncthreads();
#pragma unroll 8
        for (int k = 0; k < 64; k++) {
            float4 b = *(float4*)&Ws[k * DD + c];
            float a0 = As[r0 + 0][kb * 64 + k];
            float a1 = As[r0 + 1][kb * 64 + k];
            float a2 = As[r0 + 2][kb * 64 + k];
            float a3 = As[r0 + 3][kb * 64 + k];
            acc0.x = fmaf(a0, b.x, acc0.x); acc0.y = fmaf(a0, b.y, acc0.y);
            acc0.z = fmaf(a0, b.z, acc0.z); acc0.w = fmaf(a0, b.w, acc0.w);
            acc1.x = fmaf(a1, b.x, acc1.x); acc1.y = fmaf(a1, b.y, acc1.y);
            acc1.z = fmaf(a1, b.z, acc1.z); acc1.w = fmaf(a1, b.w, acc1.w);
            acc2.x = fmaf(a2, b.x, acc2.x); acc2.y = fmaf(a2, b.y, acc2.y);
            acc2.z = fmaf(a2, b.z, acc2.z); acc2.w = fmaf(a2, b.w, acc2.w);
            acc3.x = fmaf(a3, b.x, acc3.x); acc3.y = fmaf(a3, b.y, acc3.y);
            acc3.z = fmaf(a3, b.z, acc3.z); acc3.w = fmaf(a3, b.w, acc3.w);
        }
    }

    float4 bv = make_float4(0, 0, 0, 0);
    if (addBias) bv = *(const float4*)&bias[c];

    float4 accs[4] = {acc0, acc1, acc2, acc3};
#pragma unroll
    for (int r = 0; r < 4; r++) {
        int gr = row0 + r0 + r;
        if (gr < NN) {
            float4 o = accs[r];
            o.x += bv.x; o.y += bv.y; o.z += bv.z; o.w += bv.w;
            *(float4*)&C[gr * DD + c] = o;
        }
    }
}

// ---------------- per-node attention dots ----------------
__global__ void k_alpha(const float* __restrict__ a_src,
                        const float* __restrict__ a_dst) {
    int node = blockIdx.x * 8 + (threadIdx.x >> 5);
    int lane = threadIdx.x & 31;
    if (node >= NN) return;
    float4 h = *(const float4*)&g_hW[node * DD + lane * 4];
    float4 s = *(const float4*)&a_src[lane * 4];
    float4 d = *(const float4*)&a_dst[lane * 4];
    float ps = h.x * s.x + h.y * s.y + h.z * s.z + h.w * s.w;
    float pd = h.x * d.x + h.y * d.y + h.z * d.z + h.w * d.w;
#pragma unroll
    for (int o = 16; o; o >>= 1) {
        ps += __shfl_xor_sync(0xffffffffu, ps, o);
        pd += __shfl_xor_sync(0xffffffffu, pd, o);
    }
    if (lane == 0) {
        g_as[node] = ps;
        g_ad[node] = pd;
    }
}

// ---------------- GAT aggregation: softmax over incoming edges + self loop --
// reads g_hW/g_as/g_ad, writes g_h = relu(agg + bias)
__global__ void k_agg(const float* __restrict__ bias) {
    int node = blockIdx.x * 8 + (threadIdx.x >> 5);
    int lane = threadIdx.x & 31;
    if (node >= NN) return;

    int beg = g_off[node];
    int end = g_off[node + 1];
    float adi = g_ad[node];
    float eself = lrelu(g_as[node] + adi);

    // pass 1: exact max (incl. self loop)
    float m = eself;
    for (int t = beg + lane; t < end; t += 32) {
        float e = lrelu(g_as[g_nbr[t]] + adi);
        m = fmaxf(m, e);
    }
#pragma unroll
    for (int o = 16; o; o >>= 1)
        m = fmaxf(m, __shfl_xor_sync(0xffffffffu, m, o));

    // pass 2: denominator
    float ssum = 0.f;
    for (int t = beg + lane; t < end; t += 32)
        ssum += __expf(lrelu(g_as[g_nbr[t]] + adi) - m);
#pragma unroll
    for (int o = 16; o; o >>= 1)
        ssum += __shfl_xor_sync(0xffffffffu, ssum, o);
    ssum += __expf(eself - m);
    float inv = __fdividef(1.f, ssum);

    // pass 3: weighted gather (whole warp per neighbor row, float4/lane)
    int c = lane << 2;
    float wself = __expf(eself - m) * inv;
    float4 hv = *(const float4*)&g_hW[node * DD + c];
    float4 acc = make_float4(wself * hv.x, wself * hv.y, wself * hv.z, wself * hv.w);

    for (int t = beg; t < end; t++) {
        int j = g_nbr[t];
        float wj = __expf(lrelu(g_as[j] + adi) - m) * inv;
        float4 v = *(const float4*)&g_hW[j * DD + c];
        acc.x = fmaf(wj, v.x, acc.x);
        acc.y = fmaf(wj, v.y, acc.y);
        acc.z = fmaf(wj, v.z, acc.z);
        acc.w = fmaf(wj, v.w, acc.w);
    }

    float4 bv = *(const float4*)&bias[c];
    acc.x = fmaxf(acc.x + bv.x, 0.f);
    acc.y = fmaxf(acc.y + bv.y, 0.f);
    acc.z = fmaxf(acc.z + bv.z, 0.f);
    acc.w = fmaxf(acc.w + bv.w, 0.f);
    *(float4*)&g_h[node * DD + c] = acc;
}

// ---------------- global mean pool (sums + counts) ----------------
__global__ void k_pool(const int* __restrict__ batch) {
    int node = blockIdx.x * 8 + (threadIdx.x >> 5);
    int lane = threadIdx.x & 31;
    if (node >= NN) return;
    int b = batch[node];
    float4 v = *(const float4*)&g_h[node * DD + lane * 4];
    atomicAdd(&g_pool[b * DD + lane * 4 + 0], v.x);
    atomicAdd(&g_pool[b * DD + lane * 4 + 1], v.y);
    atomicAdd(&g_pool[b * DD + lane * 4 + 2], v.z);
    atomicAdd(&g_pool[b * DD + lane * 4 + 3], v.w);
    if (lane == 0) atomicAdd(&g_cnt[b], 1.f);
}

// ---------------- final linear: out[g] = (pool[g]/cnt[g]) . out_w + out_b ---
__global__ void k_final(const float* __restrict__ out_w,
                        const float* __restrict__ out_b,
                        float* __restrict__ out) {
    int g = blockIdx.x;
    int t = threadIdx.x;  // 128
    float v = g_pool[g * DD + t] * out_w[t];
    __shared__ float sh[4];
#pragma unroll
    for (int o = 16; o; o >>= 1) v += __shfl_xor_sync(0xffffffffu, v, o);
    if ((t & 31) == 0) sh[t >> 5] = v;
    __syncthreads();
    if (t == 0) {
        float s = sh[0] + sh[1] + sh[2] + sh[3];
        out[g] = s / g_cnt[g] + out_b[0];
    }
}

// ---------------- launch ----------------
extern "C" void kernel_launch(void* const* d_in, const int* in_sizes, int n_in,
                              void* d_out, int out_size) {
    const float* x     = (const float*)d_in[0];
    const int*   ei    = (const int*)d_in[1];
    const int*   batch = (const int*)d_in[2];
    const float* lin_w = (const float*)d_in[3];
    const float* lin_b = (const float*)d_in[4];
    const float* w1    = (const float*)d_in[5];
    const float* as1   = (const float*)d_in[6];
    const float* ad1   = (const float*)d_in[7];
    const float* b1    = (const float*)d_in[8];
    const float* w2    = (const float*)d_in[9];
    const float* as2   = (const float*)d_in[10];
    const float* ad2   = (const float*)d_in[11];
    const float* b2    = (const float*)d_in[12];
    const float* ow    = (const float*)d_in[13];
    const float* ob    = (const float*)d_in[14];
    float* out = (float*)d_out;

    const int* src = ei;        // edge_index[0]
    const int* dst = ei + EE;   // edge_index[1]

    int gemm_blocks = (NN + 31) / 32;
    int node_blocks = (NN + 7) / 8;
    int edge_blocks = (EE + 255) / 256;

    k_zero<<<(NN + 255) / 256, 256>>>();
    k_count<<<edge_blocks, 256>>>(dst);
    k_scan<<<1, 1024>>>();
    k_fill<<<edge_blocks, 256>>>(src, dst);

    // input projection: g_h = x @ lin_w + lin_b
    k_gemm<<<gemm_blocks, 256>>>(x, 1, lin_w, lin_b, 1, 1);

    // GAT layer 1
    k_gemm<<<gemm_blocks, 256>>>(nullptr, 0, w1, nullptr, 0, 0);  // g_hW = g_h @ w1
    k_alpha<<<node_blocks, 256>>>(as1, ad1);
    k_agg<<<node_blocks, 256>>>(b1);                              // g_h = relu(agg + b1)

    // GAT layer 2
    k_gemm<<<gemm_blocks, 256>>>(nullptr, 0, w2, nullptr, 0, 0);
    k_alpha<<<node_blocks, 256>>>(as2, ad2);
    k_agg<<<node_blocks, 256>>>(b2);

    // pooling + output
    k_pool<<<node_blocks, 256>>>(batch);
    k_final<<<GG, 128>>>(ow, ob, out);
}